// round 1
// baseline (speedup 1.0000x reference)
#include <cuda_runtime.h>
#include <cstdint>

// Problem constants (from reference): B=128, T=1024, K=16, n=16, m=8, p=32
#define B_ 128
#define T_ 1024
#define K_ 16

// Output layout (float32, concatenated in reference return order):
//  A_seq  (B,T,16,16) : [0,         33554432)
//  B_seq  (B,T,16,8)  : [33554432,  50331648)
//  C_seq  (B,1,32,16) : [50331648,  50397184)
//  log_q  (B,T)       : [50397184,  50528256)
//  log_p  (B,T)       : [50528256,  50659328)

// scratch: soft regime weights y_seq (B,T,K) — 8 MB device global (no allocs allowed)
__device__ float g_yseq[(size_t)B_ * T_ * K_];

__device__ __forceinline__ float frcp(float x) {
    float r; asm("rcp.approx.f32 %0, %1;" : "=f"(r) : "f"(x)); return r;
}
__device__ __forceinline__ float fexp(float x) {
    float r; asm("ex2.approx.f32 %0, %1;" : "=f"(r) : "f"(x * 1.4426950408889634f)); return r;
}
__device__ __forceinline__ float flog(float x) {
    float r; asm("lg2.approx.f32 %0, %1;" : "=f"(r) : "f"(x)); return r * 0.6931471805599453f;
}

// ============================================================================
// Phase 1: sequential regime scan. One warp per batch chain, lane j owns
// regime j. Deferred softmax normalization: carry unnormalized exp `e` and
// 1/S from the previous step so the Σe reduce overlaps the next matvec.
// ============================================================================
__global__ __launch_bounds__(32, 1) void scan_kernel(
    const float* __restrict__ logits,   // (B,T,K,K)
    const float* __restrict__ gumbel,   // (B,T,K)
    const float* __restrict__ transP,   // (K,K)
    float* __restrict__ out_lq,         // (B,T)
    float* __restrict__ out_lp)         // (B,T)
{
    const int b = blockIdx.x;
    const int j = threadIdx.x;
    if (j >= 16) return;
    const unsigned MASK = 0xffffu;

    // log transition matrix column j, kept in registers
    float P[16];
#pragma unroll
    for (int k = 0; k < 16; k++) P[k] = flog(transP[k * 16 + j]);

    const float* Lr = logits + (size_t)b * T_ * K_ * K_;
    const float* Gr = gumbel + (size_t)b * T_ * K_;

    constexpr int PF = 4;   // prefetch depth (register double..quad buffer)
    float Lb[PF][16], gb[PF];
#pragma unroll
    for (int s = 0; s < PF; s++) {
#pragma unroll
        for (int k = 0; k < 16; k++) Lb[s][k] = Lr[(size_t)s * 256 + k * 16 + j];
        gb[s] = Gr[s * 16 + j];
    }

    // initial state: y_prev uniform 1/16 -> e = 1 (unnormalized), inv = 1/16
    float e = 1.0f;
    float inv = 0.0625f;

    for (int t0 = 0; t0 < T_; t0 += PF) {
#pragma unroll
        for (int s = 0; s < PF; s++) {
            const int t = t0 + s;

            // matvec with unnormalized previous weights:
            // lr_j = sum_k e_k * L[k][j],  wr_j = sum_k e_k * logP[k][j]
            float lr = 0.0f, wr = 0.0f;
#pragma unroll
            for (int k = 0; k < 16; k++) {
                float ek = __shfl_sync(MASK, e, k, 16);
                lr = fmaf(ek, Lb[s][k], lr);
                wr = fmaf(ek, P[k], wr);
            }
            const float gcur = gb[s];

            // prefetch tile for t+PF (address-independent of recurrence)
            if (t + PF < T_) {
#pragma unroll
                for (int k = 0; k < 16; k++)
                    Lb[s][k] = Lr[(size_t)(t + PF) * 256 + k * 16 + j];
                gb[s] = Gr[(t + PF) * 16 + j];
            }

            const float l = lr * inv;                 // true mixed logit
            const float w = wr * inv;                 // (y_prev^T logP)_j
            const float en = fexp(2.0f * (l + gcur)); // exp((l+g)/tau), tau=0.5, no max-sub (range safe)
            const float el = fexp(l);                 // for logsumexp(l)

            // fused 4-value butterfly reduce; only r1 (=S) is on the critical path
            float r1 = en, r2 = en * l, r3 = en * w, r4 = el;
#pragma unroll
            for (int d = 1; d < 16; d <<= 1) {
                r1 += __shfl_xor_sync(MASK, r1, d, 16);
                r2 += __shfl_xor_sync(MASK, r2, d, 16);
                r3 += __shfl_xor_sync(MASK, r3, d, 16);
                r4 += __shfl_xor_sync(MASK, r4, d, 16);
            }
            const float invn = frcp(r1);

            g_yseq[((size_t)b * T_ + t) * 16 + j] = en * invn;
            if (j == 0) {
                // lq = dot(y,l) - log(sum exp l)   (since sum y = 1)
                out_lq[(size_t)b * T_ + t] = fmaf(r2, invn, -flog(r4));
                // lp = y_prev^T logP y ; t=0 uses uniform prior log(1/16)
                out_lp[(size_t)b * T_ + t] = (t == 0) ? -2.7725887222397811f
                                                      : r3 * invn;
            }
            e = en;
            inv = invn;
        }
    }
}

// ============================================================================
// Phase 2: parameter mixing. A_seq[b,t,i,j] = sum_k y[b,t,k] A[k,i,j]
//          B_seq[b,t,n,m] = sum_k y[b,t,k] Bm[k,n,m]
// Thread o keeps its 16 coefficients in registers; y broadcast via smem.
// Writes are fully coalesced (threads 0..255 -> A row, 256..383 -> B row).
// ============================================================================
__global__ __launch_bounds__(384, 4) void mix_kernel(
    const float* __restrict__ A,     // (K,16,16)
    const float* __restrict__ Bm,    // (K,16,8)
    float* __restrict__ outA,        // (B,T,16,16)
    float* __restrict__ outB)        // (B,T,16,8)
{
    constexpr int TS = 32;           // timesteps per block
    const int o = threadIdx.x;       // 0..383 : 0..255 -> A elem, 256..383 -> B elem
    const size_t bt0 = (size_t)blockIdx.x * TS;

    float coef[16];
    if (o < 256) {
#pragma unroll
        for (int k = 0; k < 16; k++) coef[k] = A[k * 256 + o];
    } else {
#pragma unroll
        for (int k = 0; k < 16; k++) coef[k] = Bm[k * 128 + (o - 256)];
    }

    __shared__ __align__(16) float ys[TS * 16];
    for (int i = o; i < TS * 16; i += 384) ys[i] = g_yseq[bt0 * 16 + i];
    __syncthreads();

#pragma unroll 4
    for (int s = 0; s < TS; s++) {
        const float4* yv = (const float4*)&ys[s * 16];
        const float4 y0 = yv[0], y1 = yv[1], y2 = yv[2], y3 = yv[3];
        float acc;
        acc  = coef[0]  * y0.x; acc = fmaf(coef[1],  y0.y, acc);
        acc  = fmaf(coef[2],  y0.z, acc); acc = fmaf(coef[3],  y0.w, acc);
        acc  = fmaf(coef[4],  y1.x, acc); acc = fmaf(coef[5],  y1.y, acc);
        acc  = fmaf(coef[6],  y1.z, acc); acc = fmaf(coef[7],  y1.w, acc);
        acc  = fmaf(coef[8],  y2.x, acc); acc = fmaf(coef[9],  y2.y, acc);
        acc  = fmaf(coef[10], y2.z, acc); acc = fmaf(coef[11], y2.w, acc);
        acc  = fmaf(coef[12], y3.x, acc); acc = fmaf(coef[13], y3.y, acc);
        acc  = fmaf(coef[14], y3.z, acc); acc = fmaf(coef[15], y3.w, acc);
        const size_t bt = bt0 + s;
        if (o < 256) outA[bt * 256 + o] = acc;
        else         outB[bt * 128 + (o - 256)] = acc;
    }
}

// ============================================================================
// Phase 3: C_seq = broadcast of Cm[0] (32x16) to (B,1,32,16)
// ============================================================================
__global__ void c_kernel(const float* __restrict__ Cm, float* __restrict__ outC)
{
    const int i = blockIdx.x * blockDim.x + threadIdx.x;
    if (i < B_ * 512) outC[i] = Cm[i & 511];
}

extern "C" void kernel_launch(void* const* d_in, const int* in_sizes, int n_in,
                              void* d_out, int out_size)
{
    const float* logits = (const float*)d_in[0];  // (B,T,K,K)
    const float* gumbel = (const float*)d_in[1];  // (B,T,K)
    const float* A      = (const float*)d_in[2];  // (K,16,16)
    const float* Bm     = (const float*)d_in[3];  // (K,16,8)
    const float* Cm     = (const float*)d_in[4];  // (K,32,16)
    const float* transP = (const float*)d_in[5];  // (K,K)

    float* out   = (float*)d_out;
    float* outA  = out;
    float* outB  = out + (size_t)33554432;
    float* outC  = out + (size_t)50331648;
    float* outLQ = out + (size_t)50397184;
    float* outLP = out + (size_t)50528256;

    scan_kernel<<<B_, 32>>>(logits, gumbel, transP, outLQ, outLP);
    mix_kernel<<<(B_ * T_) / 32, 384>>>(A, Bm, outA, outB);
    c_kernel<<<64, 1024>>>(Cm, outC);
}

// round 4
// speedup vs baseline: 2.0336x; 2.0336x over previous
#include <cuda_runtime.h>
#include <cstdint>

// B=128, T=1024, K=16, n=16, m=8, p=32
#define B_ 128
#define T_ 1024
#define K_ 16
#define RING 8

// Output layout (float32):
//  A_seq  (B,T,16,16) : [0,         33554432)
//  B_seq  (B,T,16,8)  : [33554432,  50331648)
//  C_seq  (B,1,32,16) : [50331648,  50397184)
//  log_q  (B,T)       : [50397184,  50528256)
//  log_p  (B,T)       : [50528256,  50659328)

// Scratch (no allocs allowed): raw per-step values from the scan
__device__ float g_e[(size_t)B_ * T_ * K_];   // unnormalized softmax numerators
__device__ float g_l[(size_t)B_ * T_ * K_];   // mixed logits l_j
__device__ float g_w[(size_t)B_ * T_ * K_];   // (y_prev^T logP)_j

__device__ __forceinline__ float frcp(float x) {
    float r; asm("rcp.approx.f32 %0, %1;" : "=f"(r) : "f"(x)); return r;
}
__device__ __forceinline__ float fexp2(float x) {
    float r; asm("ex2.approx.f32 %0, %1;" : "=f"(r) : "f"(x)); return r;
}
__device__ __forceinline__ float fexp(float x) {
    return fexp2(x * 1.4426950408889634f);
}
__device__ __forceinline__ float flog(float x) {
    float r; asm("lg2.approx.f32 %0, %1;" : "=f"(r) : "f"(x)); return r * 0.6931471805599453f;
}
__device__ __forceinline__ uint32_t sa(const void* p) {
    uint32_t a;
    asm("{ .reg .u64 t; cvta.to.shared.u64 t, %1; cvt.u32.u64 %0, t; }" : "=r"(a) : "l"(p));
    return a;
}
__device__ __forceinline__ void cp16(uint32_t dst, const void* src) {
    asm volatile("cp.async.cg.shared.global [%0], [%1], 16;" :: "r"(dst), "l"(src));
}
__device__ __forceinline__ void cp4p(uint32_t dst, const void* src, int pred) {
    asm volatile("{ .reg .pred p; setp.ne.u32 p, %2, 0;"
                 " @p cp.async.ca.shared.global [%0], [%1], 4; }"
                 :: "r"(dst), "l"(src), "r"(pred));
}

// ============================================================================
// Phase 1: sequential regime scan. One warp per chain. Every lane holds the
// FULL unnormalized state e[16] in registers (float4 x4). Low lanes (0-15)
// run the logits matvec, high lanes (16-31) run the logP matvec with the SAME
// instructions (per-lane smem base pointer selects logits tile vs P tile).
// State exchange: 1 STS + syncwarp + 4 LDS.128. Sum S = local 15-FADD tree.
// Logits stream in through a depth-8 cp.async ring (no per-warp LDG cap).
// ============================================================================
__global__ __launch_bounds__(32, 1) void scan_kernel(
    const float* __restrict__ logits,   // (B,T,16,16)
    const float* __restrict__ gumbel,   // (B,T,16)
    const float* __restrict__ transP)   // (16,16)
{
    __shared__ __align__(16) float s_stage[RING][272];  // 256 tile + 16 gumbel
    __shared__ __align__(16) float s_P[256];            // logP, tile-layout
    __shared__ __align__(16) float s_ex[2][16];         // state exchange, dbl-buf

    const int b    = blockIdx.x;
    const int lane = threadIdx.x;
    const int j    = lane & 15;
    const bool lo  = lane < 16;
    const int lop  = lo ? 1 : 0;
    const float KLOG2 = 2.8853900817779268f;   // 2/tau * log2(e), tau=0.5

    const float* gL = logits + (size_t)b * (T_ * 256);
    const float* gG = gumbel + (size_t)b * (T_ * 16);

    // low lanes populate s_P (column j of log transP), layout matches tiles
    if (lo) {
#pragma unroll
        for (int k = 0; k < 16; ++k)
            s_P[k * 16 + j] = flog(transP[k * 16 + j]);
    }

    // prime cp.async ring: groups for t = 0..RING-2
    const uint32_t st_base = sa(&s_stage[0][0]);
#pragma unroll
    for (int u = 0; u < RING - 1; ++u) {
        uint32_t dst = st_base + u * 1088;
        const char* src = (const char*)(gL + u * 256);
        cp16(dst + lane * 16, src + lane * 16);
        cp16(dst + 512 + lane * 16, src + 512 + lane * 16);
        cp4p(dst + 1024 + j * 4, (const char*)(gG + u * 16) + j * 4, lop);
        asm volatile("cp.async.commit_group;");
    }
    asm volatile("cp.async.wait_group %0;" :: "n"(RING - 2));
    __syncwarp();

    // initial column regs for t=0: low <- tile slot 0, high <- P
    float Lc[16];
    {
        const float* bp = lo ? &s_stage[0][0] : s_P;
#pragma unroll
        for (int k = 0; k < 16; ++k) Lc[k] = bp[k * 16 + j];
    }
    float Kg = s_stage[0][256 + j] * KLOG2;

    // initial state: y_prev uniform -> e=1 (all), inv = 1/16
    float4 ev0 = make_float4(1.f, 1.f, 1.f, 1.f);
    float4 ev1 = ev0, ev2 = ev0, ev3 = ev0;
    float inv = 0.0625f;

    float* pa = (lo ? g_l : g_w) + (size_t)b * (T_ * 16) + j;
    float* pe = g_e + (size_t)b * (T_ * 16) + j;
    const char* gsrc  = (const char*)(gL + (RING - 1) * 256);
    const char* gsrcg = (const char*)(gG + (RING - 1) * 16);

    for (int tt = 0; tt < T_ / RING; ++tt) {
#pragma unroll
        for (int s = 0; s < RING; ++s) {
            const int t = tt * RING + s;

            // prefetch tile for t+RING-1 into slot (s-1)&7
            if (t + RING - 1 < T_) {
                uint32_t dst = st_base + ((s + RING - 1) & (RING - 1)) * 1088;
                const char* src = gsrc + s * 1024;
                cp16(dst + lane * 16, src + lane * 16);
                cp16(dst + 512 + lane * 16, src + 512 + lane * 16);
                cp4p(dst + 1024 + j * 4, gsrcg + s * 64 + j * 4, lop);
            }
            asm volatile("cp.async.commit_group;");

            // matvec: low lanes -> mixed logits, high lanes -> logP mix
            float a0 = Lc[0] * ev0.x;
            a0 = fmaf(Lc[4],  ev1.x, a0);
            a0 = fmaf(Lc[8],  ev2.x, a0);
            a0 = fmaf(Lc[12], ev3.x, a0);
            float a1 = Lc[1] * ev0.y;
            a1 = fmaf(Lc[5],  ev1.y, a1);
            a1 = fmaf(Lc[9],  ev2.y, a1);
            a1 = fmaf(Lc[13], ev3.y, a1);
            float a2 = Lc[2] * ev0.z;
            a2 = fmaf(Lc[6],  ev1.z, a2);
            a2 = fmaf(Lc[10], ev2.z, a2);
            a2 = fmaf(Lc[14], ev3.z, a2);
            float a3 = Lc[3] * ev0.w;
            a3 = fmaf(Lc[7],  ev1.w, a3);
            a3 = fmaf(Lc[11], ev2.w, a3);
            a3 = fmaf(Lc[15], ev3.w, a3);
            const float lrw = (a0 + a1) + (a2 + a3);

            const float val = lrw * inv;       // low: l_j, high: w_j
            pa[s * 16] = val;

            const float en = fexp2(fmaf(val, KLOG2, Kg)); // exp((l+g)/tau)
            if (lo) {
                pe[s * 16] = en;
                s_ex[s & 1][j] = en;
            }

            asm volatile("cp.async.wait_group %0;" :: "n"(RING - 2));
            __syncwarp();

            // gather new full state
            const float4* ep = (const float4*)s_ex[s & 1];
            ev0 = ep[0]; ev1 = ep[1]; ev2 = ep[2]; ev3 = ep[3];

            // local tree-sum for S, then 1/S
            float t0 = (ev0.x + ev0.y) + (ev0.z + ev0.w);
            float t1 = (ev1.x + ev1.y) + (ev1.z + ev1.w);
            float t2 = (ev2.x + ev2.y) + (ev2.z + ev2.w);
            float t3 = (ev3.x + ev3.y) + (ev3.z + ev3.w);
            inv = frcp((t0 + t1) + (t2 + t3));

            // next step's column regs + scaled gumbel
            const int ns = (s + 1) & (RING - 1);
            const float* bp = lo ? &s_stage[ns][0] : s_P;
#pragma unroll
            for (int k = 0; k < 16; ++k) Lc[k] = bp[k * 16 + j];
            Kg = s_stage[ns][256 + j] * KLOG2;
        }
        gsrc  += RING * 1024;
        gsrcg += RING * 64;
        pa    += RING * 16;
        pe    += RING * 16;
    }
}

// ============================================================================
// Phase 2: fixup (normalize y, lq, lp) + parameter mixing with float2 stores.
// Block handles 32 timesteps; threads 0..31 do the fixup, then all 384 mix.
// ============================================================================
__global__ __launch_bounds__(384) void mix_kernel(
    const float* __restrict__ A,     // (16,16,16)
    const float* __restrict__ Bm,    // (16,16,8)
    float* __restrict__ outA,        // (B,T,16,16)
    float* __restrict__ outB,        // (B,T,16,8)
    float* __restrict__ outLQ,       // (B,T)
    float* __restrict__ outLP)       // (B,T)
{
    const int tid = threadIdx.x;
    const int bt0 = blockIdx.x * 32;
    __shared__ __align__(16) float ys[32 * 16];

    const int slot = tid % 192;          // 0..127 -> A float2, 128..191 -> B float2
    const int srel = tid / 192;          // 0/1: even/odd timestep
    float2 coef[16];
    if (slot < 128) {
#pragma unroll
        for (int k = 0; k < 16; ++k) coef[k] = ((const float2*)A)[k * 128 + slot];
    } else {
#pragma unroll
        for (int k = 0; k < 16; ++k) coef[k] = ((const float2*)Bm)[k * 64 + (slot - 128)];
    }

    if (tid < 32) {
        const int bt = bt0 + tid;
        const float4* er = (const float4*)(g_e + (size_t)bt * 16);
        float4 e0 = er[0], e1 = er[1], e2 = er[2], e3 = er[3];
        float S = (((e0.x + e0.y) + (e0.z + e0.w)) + ((e1.x + e1.y) + (e1.z + e1.w)))
                + (((e2.x + e2.y) + (e2.z + e2.w)) + ((e3.x + e3.y) + (e3.z + e3.w)));
        const float inv = frcp(S);
        float y[16];
        y[0]=e0.x*inv; y[1]=e0.y*inv; y[2]=e0.z*inv; y[3]=e0.w*inv;
        y[4]=e1.x*inv; y[5]=e1.y*inv; y[6]=e1.z*inv; y[7]=e1.w*inv;
        y[8]=e2.x*inv; y[9]=e2.y*inv; y[10]=e2.z*inv; y[11]=e2.w*inv;
        y[12]=e3.x*inv; y[13]=e3.y*inv; y[14]=e3.z*inv; y[15]=e3.w*inv;
        float4* yd = (float4*)&ys[tid * 16];
        yd[0] = make_float4(y[0], y[1], y[2], y[3]);
        yd[1] = make_float4(y[4], y[5], y[6], y[7]);
        yd[2] = make_float4(y[8], y[9], y[10], y[11]);
        yd[3] = make_float4(y[12], y[13], y[14], y[15]);

        const float4* lr = (const float4*)(g_l + (size_t)bt * 16);
        float4 l0 = lr[0], l1 = lr[1], l2 = lr[2], l3 = lr[3];
        float lv[16] = { l0.x,l0.y,l0.z,l0.w, l1.x,l1.y,l1.z,l1.w,
                         l2.x,l2.y,l2.z,l2.w, l3.x,l3.y,l3.z,l3.w };
        float dot = 0.f, z = 0.f;
#pragma unroll
        for (int k = 0; k < 16; ++k) {
            dot = fmaf(y[k], lv[k], dot);
            z  += fexp(lv[k]);
        }
        const float lq = dot - flog(z);

        const float4* wr = (const float4*)(g_w + (size_t)bt * 16);
        float4 w0 = wr[0], w1 = wr[1], w2 = wr[2], w3 = wr[3];
        float wv[16] = { w0.x,w0.y,w0.z,w0.w, w1.x,w1.y,w1.z,w1.w,
                         w2.x,w2.y,w2.z,w2.w, w3.x,w3.y,w3.z,w3.w };
        float lp = 0.f;
#pragma unroll
        for (int k = 0; k < 16; ++k) lp = fmaf(y[k], wv[k], lp);
        if ((bt & (T_ - 1)) == 0) lp = -2.7725887222397811f;  // -log(16) at t=0

        outLQ[bt] = lq;
        outLP[bt] = lp;
    }
    __syncthreads();

#pragma unroll 4
    for (int i = 0; i < 16; ++i) {
        const int s = 2 * i + srel;
        const float4* yv = (const float4*)&ys[s * 16];
        const float4 y0 = yv[0], y1 = yv[1], y2 = yv[2], y3 = yv[3];
        float2 acc;
        acc.x = coef[0].x * y0.x;            acc.y = coef[0].y * y0.x;
        acc.x = fmaf(coef[1].x,  y0.y, acc.x); acc.y = fmaf(coef[1].y,  y0.y, acc.y);
        acc.x = fmaf(coef[2].x,  y0.z, acc.x); acc.y = fmaf(coef[2].y,  y0.z, acc.y);
        acc.x = fmaf(coef[3].x,  y0.w, acc.x); acc.y = fmaf(coef[3].y,  y0.w, acc.y);
        acc.x = fmaf(coef[4].x,  y1.x, acc.x); acc.y = fmaf(coef[4].y,  y1.x, acc.y);
        acc.x = fmaf(coef[5].x,  y1.y, acc.x); acc.y = fmaf(coef[5].y,  y1.y, acc.y);
        acc.x = fmaf(coef[6].x,  y1.z, acc.x); acc.y = fmaf(coef[6].y,  y1.z, acc.y);
        acc.x = fmaf(coef[7].x,  y1.w, acc.x); acc.y = fmaf(coef[7].y,  y1.w, acc.y);
        acc.x = fmaf(coef[8].x,  y2.x, acc.x); acc.y = fmaf(coef[8].y,  y2.x, acc.y);
        acc.x = fmaf(coef[9].x,  y2.y, acc.x); acc.y = fmaf(coef[9].y,  y2.y, acc.y);
        acc.x = fmaf(coef[10].x, y2.z, acc.x); acc.y = fmaf(coef[10].y, y2.z, acc.y);
        acc.x = fmaf(coef[11].x, y2.w, acc.x); acc.y = fmaf(coef[11].y, y2.w, acc.y);
        acc.x = fmaf(coef[12].x, y3.x, acc.x); acc.y = fmaf(coef[12].y, y3.x, acc.y);
        acc.x = fmaf(coef[13].x, y3.y, acc.x); acc.y = fmaf(coef[13].y, y3.y, acc.y);
        acc.x = fmaf(coef[14].x, y3.z, acc.x); acc.y = fmaf(coef[14].y, y3.z, acc.y);
        acc.x = fmaf(coef[15].x, y3.w, acc.x); acc.y = fmaf(coef[15].y, y3.w, acc.y);
        const size_t bt = (size_t)bt0 + s;
        if (slot < 128) ((float2*)outA)[bt * 128 + slot] = acc;
        else            ((float2*)outB)[bt * 64 + (slot - 128)] = acc;
    }
}

// ============================================================================
// Phase 3: C_seq broadcast
// ============================================================================
__global__ void c_kernel(const float* __restrict__ Cm, float* __restrict__ outC)
{
    const int i = blockIdx.x * blockDim.x + threadIdx.x;
    if (i < B_ * 512) outC[i] = Cm[i & 511];
}

extern "C" void kernel_launch(void* const* d_in, const int* in_sizes, int n_in,
                              void* d_out, int out_size)
{
    const float* logits = (const float*)d_in[0];
    const float* gumbel = (const float*)d_in[1];
    const float* A      = (const float*)d_in[2];
    const float* Bm     = (const float*)d_in[3];
    const float* Cm     = (const float*)d_in[4];
    const float* transP = (const float*)d_in[5];

    float* out   = (float*)d_out;
    float* outA  = out;
    float* outB  = out + (size_t)33554432;
    float* outC  = out + (size_t)50331648;
    float* outLQ = out + (size_t)50397184;
    float* outLP = out + (size_t)50528256;

    scan_kernel<<<B_, 32>>>(logits, gumbel, transP);
    mix_kernel<<<(B_ * T_) / 32, 384>>>(A, Bm, outA, outB, outLQ, outLP);
    c_kernel<<<64, 1024>>>(Cm, outC);
}